// round 8
// baseline (speedup 1.0000x reference)
#include <cuda_runtime.h>
#include <math.h>

#define D_INNER 8192
#define D_MODEL 4096
#define DT_RANK 8
#define D_STATE 16
#define XP_ROWS (DT_RANK + 2 * D_STATE)  // 40

// Prefetch plan: stage the first PREF_TOTAL floats of W_out into L2 during
// K2/K3 (DRAM-idle window). K2 extra blocks cover [0, PREF_K2), K3 extra
// blocks cover [PREF_K2, PREF_K2 + PREF_K3).
#define PREF_K2_BLOCKS 64
#define PREF_K2_PER_BLOCK (32768)             // floats: 128 KB -> 8 MB total
#define PREF_K3_BLOCKS 96
#define PREF_K3_PER_BLOCK (32768)             // floats: 128 KB -> 12 MB total

// Scratch (allocation-free rule: __device__ globals)
__device__ float g_z[D_INNER];          // z gate half of xz
__device__ float g_xconv[D_INNER];      // silu(conv(x_branch))
__device__ float g_xp[XP_ROWS];         // 40
__device__ float g_y[D_INNER];          // 8192
__device__ float g_sink[256];           // prefetch DCE-killer sink

__device__ __forceinline__ float silu_fast(float v) {
    return v / (1.0f + __expf(-v));
}

__device__ __forceinline__ float dot4(float4 w, float4 v) {
    return w.x * v.x + w.y * v.y + w.z * v.z + w.w * v.w;
}

// Streaming partial dot over `len4` float4, 4-way batched, lane-strided.
__device__ __forceinline__ float partial_dot(const float4* __restrict__ Wr,
                                             const float4* __restrict__ xv,
                                             int lane, int len4) {
    float acc0 = 0.f, acc1 = 0.f, acc2 = 0.f, acc3 = 0.f;
    #pragma unroll
    for (int i = lane; i < len4; i += 128) {
        float4 w0 = __ldcs(&Wr[i]);
        float4 w1 = __ldcs(&Wr[i + 32]);
        float4 w2 = __ldcs(&Wr[i + 64]);
        float4 w3 = __ldcs(&Wr[i + 96]);
        float4 v0 = xv[i], v1 = xv[i + 32], v2 = xv[i + 64], v3 = xv[i + 96];
        acc0 += dot4(w0, v0);
        acc1 += dot4(w1, v1);
        acc2 += dot4(w2, v2);
        acc3 += dot4(w3, v3);
    }
    float acc = (acc0 + acc1) + (acc2 + acc3);
    #pragma unroll
    for (int o = 16; o; o >>= 1) acc += __shfl_xor_sync(0xffffffffu, acc, o);
    return acc;
}

// Pull `count4` float4 of W into L2 (evict-normal) starting at float offset.
__device__ __forceinline__ void l2_prefetch(const float* __restrict__ W,
                                            size_t off_floats, int count4,
                                            int tid, int nthr, int sink_slot) {
    const float4* p = reinterpret_cast<const float4*>(W + off_floats);
    float s = 0.f;
    for (int i = tid; i < count4; i += nthr) {
        float4 v = __ldcg(&p[i]);
        s += v.x + v.y + v.z + v.w;
    }
    // defeat DCE; deterministic value, never read by compute
    if (tid == 0) g_sink[sink_slot] = s;
}

// ---------------------------------------------------------------------------
// K1: xz = W_in @ x, fused conv + SiLU epilogue.
// TWO warps per row (half-row each): 32768 warp-tasks, 4096 blocks.
// ---------------------------------------------------------------------------
__global__ __launch_bounds__(256) void gemv_win_fused(
    const float* __restrict__ W,
    const float* __restrict__ x,
    const float* __restrict__ conv_buffer,
    const float* __restrict__ conv_w,
    const float* __restrict__ conv_b) {
    int wid  = threadIdx.x >> 5;
    int lane = threadIdx.x & 31;
    int row  = blockIdx.x * 4 + (wid >> 1);
    int half = wid & 1;
    const int h4 = D_MODEL / 8;  // 512 float4 per half-row

    const float4* Wr = reinterpret_cast<const float4*>(W + (size_t)row * D_MODEL)
                     + half * h4;
    const float4* xv = reinterpret_cast<const float4*>(x) + half * h4;

    float acc = partial_dot(Wr, xv, lane, h4);

    __shared__ float part[8];
    if (lane == 0) part[wid] = acc;
    __syncthreads();

    if (threadIdx.x < 4) {
        int r = blockIdx.x * 4 + threadIdx.x;
        float s = part[2 * threadIdx.x] + part[2 * threadIdx.x + 1];
        if (r < D_INNER) {
            // conv epilogue: conv_in = [buf1, buf2, xb, xb]
            float b1 = conv_buffer[r * 3 + 1];
            float b2 = conv_buffer[r * 3 + 2];
            float4 w = reinterpret_cast<const float4*>(conv_w)[r];
            float cs = b1 * w.x + b2 * w.y + s * (w.z + w.w) + conv_b[r];
            g_xconv[r] = silu_fast(cs);
        } else {
            g_z[r - D_INNER] = s;
        }
    }
}

// ---------------------------------------------------------------------------
// K2: xp = W_xp @ x_conv (blocks [0,40)) + W_out L2 prefetch (blocks [40,104)).
// ---------------------------------------------------------------------------
__global__ __launch_bounds__(1024) void gemv_xp(const float* __restrict__ W,
                                                const float* __restrict__ W_out) {
    if (blockIdx.x >= XP_ROWS) {
        int pb = blockIdx.x - XP_ROWS;
        l2_prefetch(W_out, (size_t)pb * PREF_K2_PER_BLOCK,
                    PREF_K2_PER_BLOCK / 4, threadIdx.x, 1024, pb & 255);
        return;
    }
    int row = blockIdx.x;
    const float4* Wr = reinterpret_cast<const float4*>(W + (size_t)row * D_INNER);
    const float4* xv = reinterpret_cast<const float4*>(g_xconv);
    float4 w0 = __ldcs(&Wr[threadIdx.x]);
    float4 w1 = __ldcs(&Wr[threadIdx.x + 1024]);
    float4 v0 = xv[threadIdx.x];
    float4 v1 = xv[threadIdx.x + 1024];
    float acc = dot4(w0, v0) + dot4(w1, v1);

    __shared__ float red[32];
    int lane = threadIdx.x & 31;
    int wid  = threadIdx.x >> 5;
    #pragma unroll
    for (int o = 16; o; o >>= 1) acc += __shfl_xor_sync(0xffffffffu, acc, o);
    if (lane == 0) red[wid] = acc;
    __syncthreads();
    if (wid == 0) {
        float v = red[lane];
        #pragma unroll
        for (int o = 16; o; o >>= 1) v += __shfl_xor_sync(0xffffffffu, v, o);
        if (lane == 0) g_xp[row] = v;
    }
}

// ---------------------------------------------------------------------------
// K3: state update + y (blocks [0,128)); W_out prefetch (blocks [128,224)).
// ---------------------------------------------------------------------------
__global__ __launch_bounds__(64) void ssm_update_kernel(
    const float* __restrict__ W_dt,
    const float* __restrict__ b_dt,
    const float* __restrict__ A_log,
    const float* __restrict__ ssm_state,
    const float* __restrict__ D_param,
    const float* __restrict__ W_out_pref,
    float* __restrict__ new_h_out) {
    if (blockIdx.x >= D_INNER / 64) {
        int pb = blockIdx.x - D_INNER / 64;
        size_t base = (size_t)PREF_K2_BLOCKS * PREF_K2_PER_BLOCK;
        l2_prefetch(W_out_pref, base + (size_t)pb * PREF_K3_PER_BLOCK,
                    PREF_K3_PER_BLOCK / 4, threadIdx.x, 64, pb & 255);
        return;
    }

    __shared__ float s_xp[XP_ROWS];
    if (threadIdx.x < XP_ROWS) s_xp[threadIdx.x] = g_xp[threadIdx.x];
    __syncthreads();

    int i = blockIdx.x * 64 + threadIdx.x;

    const float4* wd = reinterpret_cast<const float4*>(W_dt + (size_t)i * DT_RANK);
    float4 w0 = wd[0], w1 = wd[1];
    float acc = b_dt[i]
        + w0.x * s_xp[0] + w0.y * s_xp[1] + w0.z * s_xp[2] + w0.w * s_xp[3]
        + w1.x * s_xp[4] + w1.y * s_xp[5] + w1.z * s_xp[6] + w1.w * s_xp[7];
    float dt = fmaxf(acc, 0.0f) + log1pf(__expf(-fabsf(acc)));

    float xc = g_xconv[i];
    float dtx = dt * xc;
    const float* B = s_xp + DT_RANK;
    const float* C = s_xp + DT_RANK + D_STATE;

    const float4* Al = reinterpret_cast<const float4*>(A_log + (size_t)i * D_STATE);
    const float4* Hs = reinterpret_cast<const float4*>(ssm_state + (size_t)i * D_STATE);
    float4* Ho = reinterpret_cast<float4*>(new_h_out + (size_t)i * D_STATE);

    float ysum = 0.0f;
    #pragma unroll
    for (int q = 0; q < 4; q++) {
        float4 a4 = Al[q];
        float4 h4 = Hs[q];
        float4 o4;
        o4.x = __expf(-dt * __expf(a4.x)) * h4.x + dtx * B[4 * q + 0];
        o4.y = __expf(-dt * __expf(a4.y)) * h4.y + dtx * B[4 * q + 1];
        o4.z = __expf(-dt * __expf(a4.z)) * h4.z + dtx * B[4 * q + 2];
        o4.w = __expf(-dt * __expf(a4.w)) * h4.w + dtx * B[4 * q + 3];
        ysum += o4.x * C[4 * q + 0] + o4.y * C[4 * q + 1]
              + o4.z * C[4 * q + 2] + o4.w * C[4 * q + 3];
        Ho[q] = o4;
    }

    float yv = ysum + D_param[i] * xc;
    g_y[i] = yv * silu_fast(g_z[i]);
}

// ---------------------------------------------------------------------------
// K4: out = W_out @ y : 4096 rows x 8192 cols.
// FOUR warps per row (quarter-row each): 16384 warp-tasks, 2048 blocks.
// ---------------------------------------------------------------------------
__global__ __launch_bounds__(256) void gemv_wout(const float* __restrict__ W,
                                                 float* __restrict__ out) {
    int wid  = threadIdx.x >> 5;
    int lane = threadIdx.x & 31;
    int row  = blockIdx.x * 2 + (wid >> 2);
    int quarter = wid & 3;
    const int q4 = D_INNER / 16;  // 512 float4 per quarter-row

    const float4* Wr = reinterpret_cast<const float4*>(W + (size_t)row * D_INNER)
                     + quarter * q4;
    const float4* xv = reinterpret_cast<const float4*>(g_y) + quarter * q4;

    float acc = partial_dot(Wr, xv, lane, q4);

    __shared__ float part[8];
    if (lane == 0) part[wid] = acc;
    __syncthreads();
    if (threadIdx.x < 2) {
        int b = 4 * threadIdx.x;
        out[blockIdx.x * 2 + threadIdx.x] =
            (part[b] + part[b + 1]) + (part[b + 2] + part[b + 3]);
    }
}

// ---------------------------------------------------------------------------
extern "C" void kernel_launch(void* const* d_in, const int* in_sizes, int n_in,
                              void* d_out, int out_size) {
    const float* x           = (const float*)d_in[0];
    const float* ssm_state   = (const float*)d_in[1];
    const float* conv_buffer = (const float*)d_in[2];
    const float* W_in        = (const float*)d_in[3];
    const float* conv_w      = (const float*)d_in[4];
    const float* conv_b      = (const float*)d_in[5];
    const float* W_xp        = (const float*)d_in[6];
    const float* W_dt        = (const float*)d_in[7];
    const float* b_dt        = (const float*)d_in[8];
    const float* A_log       = (const float*)d_in[9];
    const float* D_param     = (const float*)d_in[10];
    const float* W_out       = (const float*)d_in[11];

    float* out   = (float*)d_out;               // [0, 4096)
    float* new_h = (float*)d_out + D_MODEL;     // [4096, 4096 + 8192*16)

    // K1: W_in GEMV + fused conv/SiLU (2 warps/row -> 4096 blocks)
    gemv_win_fused<<<(2 * D_INNER) / 4, 256>>>(W_in, x, conv_buffer, conv_w, conv_b);

    // K2: xp GEMV (40 blocks) + W_out L2 prefetch (64 blocks)
    gemv_xp<<<XP_ROWS + PREF_K2_BLOCKS, 1024>>>(W_xp, W_out);

    // K3: state update (128 blocks) + W_out L2 prefetch (96 blocks)
    ssm_update_kernel<<<D_INNER / 64 + PREF_K3_BLOCKS, 64>>>(
        W_dt, b_dt, A_log, ssm_state, D_param, W_out, new_h);

    // K4: out = W_out @ y (4 warps/row -> 2048 blocks)
    gemv_wout<<<D_MODEL / 2, 256>>>(W_out, out);
}

// round 10
// speedup vs baseline: 1.1785x; 1.1785x over previous
#include <cuda_runtime.h>
#include <math.h>

#define D_INNER 8192
#define D_MODEL 4096
#define DT_RANK 8
#define D_STATE 16
#define XP_ROWS (DT_RANK + 2 * D_STATE)  // 40

// Scratch (allocation-free rule: __device__ globals)
__device__ float g_z[D_INNER];          // z gate half of xz
__device__ float g_xconv[D_INNER];      // silu(conv(x_branch))
__device__ float g_xp[XP_ROWS];         // 40
__device__ float g_y[D_INNER];          // 8192

__device__ __forceinline__ float silu_fast(float v) {
    return v / (1.0f + __expf(-v));
}

__device__ __forceinline__ float dot4(float4 w, float4 v) {
    return w.x * v.x + w.y * v.y + w.z * v.z + w.w * v.w;
}

// Streaming partial dot over `len4` float4, 4-way batched, lane-strided.
__device__ __forceinline__ float partial_dot(const float4* __restrict__ Wr,
                                             const float4* __restrict__ xv,
                                             int lane, int len4) {
    float acc0 = 0.f, acc1 = 0.f, acc2 = 0.f, acc3 = 0.f;
    #pragma unroll
    for (int i = lane; i < len4; i += 128) {
        float4 w0 = __ldcs(&Wr[i]);
        float4 w1 = __ldcs(&Wr[i + 32]);
        float4 w2 = __ldcs(&Wr[i + 64]);
        float4 w3 = __ldcs(&Wr[i + 96]);
        float4 v0 = xv[i], v1 = xv[i + 32], v2 = xv[i + 64], v3 = xv[i + 96];
        acc0 += dot4(w0, v0);
        acc1 += dot4(w1, v1);
        acc2 += dot4(w2, v2);
        acc3 += dot4(w3, v3);
    }
    float acc = (acc0 + acc1) + (acc2 + acc3);
    #pragma unroll
    for (int o = 16; o; o >>= 1) acc += __shfl_xor_sync(0xffffffffu, acc, o);
    return acc;
}

// ---------------------------------------------------------------------------
// K1: xz = W_in @ x, fused conv + SiLU epilogue.
// TWO warps per row (half-row each, 8 KB warp-task): 4096 blocks.
// Block = 8 warps = 4 rows. Epilogue by threads 0..3.
// ---------------------------------------------------------------------------
__global__ __launch_bounds__(256) void gemv_win_fused(
    const float* __restrict__ W,
    const float* __restrict__ x,
    const float* __restrict__ conv_buffer,
    const float* __restrict__ conv_w,
    const float* __restrict__ conv_b) {
    int wid  = threadIdx.x >> 5;
    int lane = threadIdx.x & 31;
    int row  = blockIdx.x * 4 + (wid >> 1);
    int half = wid & 1;
    const int h4 = D_MODEL / 8;  // 512 float4 per half-row

    const float4* Wr = reinterpret_cast<const float4*>(W + (size_t)row * D_MODEL)
                     + half * h4;
    const float4* xv = reinterpret_cast<const float4*>(x) + half * h4;

    float acc = partial_dot(Wr, xv, lane, h4);

    __shared__ float part[8];
    if (lane == 0) part[wid] = acc;
    __syncthreads();

    if (threadIdx.x < 4) {
        int r = blockIdx.x * 4 + threadIdx.x;
        float s = part[2 * threadIdx.x] + part[2 * threadIdx.x + 1];
        if (r < D_INNER) {
            // conv epilogue: conv_in = [buf1, buf2, xb, xb]
            float b1 = conv_buffer[r * 3 + 1];
            float b2 = conv_buffer[r * 3 + 2];
            float4 w = reinterpret_cast<const float4*>(conv_w)[r];
            float cs = b1 * w.x + b2 * w.y + s * (w.z + w.w) + conv_b[r];
            g_xconv[r] = silu_fast(cs);
        } else {
            g_z[r - D_INNER] = s;
        }
    }
}

// ---------------------------------------------------------------------------
// K2: xp = W_xp @ x_conv : 40 rows x 8192. One block of 1024 threads per row.
// ---------------------------------------------------------------------------
__global__ __launch_bounds__(1024) void gemv_xp(const float* __restrict__ W) {
    int row = blockIdx.x;
    const float4* Wr = reinterpret_cast<const float4*>(W + (size_t)row * D_INNER);
    const float4* xv = reinterpret_cast<const float4*>(g_xconv);
    float4 w0 = __ldcs(&Wr[threadIdx.x]);
    float4 w1 = __ldcs(&Wr[threadIdx.x + 1024]);
    float4 v0 = xv[threadIdx.x];
    float4 v1 = xv[threadIdx.x + 1024];
    float acc = dot4(w0, v0) + dot4(w1, v1);

    __shared__ float red[32];
    int lane = threadIdx.x & 31;
    int wid  = threadIdx.x >> 5;
    #pragma unroll
    for (int o = 16; o; o >>= 1) acc += __shfl_xor_sync(0xffffffffu, acc, o);
    if (lane == 0) red[wid] = acc;
    __syncthreads();
    if (wid == 0) {
        float v = red[lane];
        #pragma unroll
        for (int o = 16; o; o >>= 1) v += __shfl_xor_sync(0xffffffffu, v, o);
        if (lane == 0) g_xp[row] = v;
    }
}

// ---------------------------------------------------------------------------
// K3: dt = softplus(W_dt @ xp[:8] + b_dt); state update; y with z-gate.
// ---------------------------------------------------------------------------
__global__ __launch_bounds__(64) void ssm_update_kernel(
    const float* __restrict__ W_dt,
    const float* __restrict__ b_dt,
    const float* __restrict__ A_log,
    const float* __restrict__ ssm_state,
    const float* __restrict__ D_param,
    float* __restrict__ new_h_out) {
    __shared__ float s_xp[XP_ROWS];
    if (threadIdx.x < XP_ROWS) s_xp[threadIdx.x] = g_xp[threadIdx.x];
    __syncthreads();

    int i = blockIdx.x * 64 + threadIdx.x;

    const float4* wd = reinterpret_cast<const float4*>(W_dt + (size_t)i * DT_RANK);
    float4 w0 = wd[0], w1 = wd[1];
    float acc = b_dt[i]
        + w0.x * s_xp[0] + w0.y * s_xp[1] + w0.z * s_xp[2] + w0.w * s_xp[3]
        + w1.x * s_xp[4] + w1.y * s_xp[5] + w1.z * s_xp[6] + w1.w * s_xp[7];
    float dt = fmaxf(acc, 0.0f) + log1pf(__expf(-fabsf(acc)));

    float xc = g_xconv[i];
    float dtx = dt * xc;
    const float* B = s_xp + DT_RANK;
    const float* C = s_xp + DT_RANK + D_STATE;

    const float4* Al = reinterpret_cast<const float4*>(A_log + (size_t)i * D_STATE);
    const float4* Hs = reinterpret_cast<const float4*>(ssm_state + (size_t)i * D_STATE);
    float4* Ho = reinterpret_cast<float4*>(new_h_out + (size_t)i * D_STATE);

    float ysum = 0.0f;
    #pragma unroll
    for (int q = 0; q < 4; q++) {
        float4 a4 = Al[q];
        float4 h4 = Hs[q];
        float4 o4;
        o4.x = __expf(-dt * __expf(a4.x)) * h4.x + dtx * B[4 * q + 0];
        o4.y = __expf(-dt * __expf(a4.y)) * h4.y + dtx * B[4 * q + 1];
        o4.z = __expf(-dt * __expf(a4.z)) * h4.z + dtx * B[4 * q + 2];
        o4.w = __expf(-dt * __expf(a4.w)) * h4.w + dtx * B[4 * q + 3];
        ysum += o4.x * C[4 * q + 0] + o4.y * C[4 * q + 1]
              + o4.z * C[4 * q + 2] + o4.w * C[4 * q + 3];
        Ho[q] = o4;
    }

    float yv = ysum + D_param[i] * xc;
    g_y[i] = yv * silu_fast(g_z[i]);
}

// ---------------------------------------------------------------------------
// K4: out = W_out @ y : 4096 rows x 8192 cols.
// Block = 128 thr = 4 warps = ONE row (quarter-row / 8 KB per warp).
// 4096 blocks for fine scheduling granularity; smem combine, deterministic.
// ---------------------------------------------------------------------------
__global__ __launch_bounds__(128) void gemv_wout(const float* __restrict__ W,
                                                 float* __restrict__ out) {
    int wid  = threadIdx.x >> 5;
    int lane = threadIdx.x & 31;
    int row  = blockIdx.x;
    const int q4 = D_INNER / 16;  // 512 float4 per quarter-row

    const float4* Wr = reinterpret_cast<const float4*>(W + (size_t)row * D_INNER)
                     + wid * q4;
    const float4* xv = reinterpret_cast<const float4*>(g_y) + wid * q4;

    float acc = partial_dot(Wr, xv, lane, q4);

    __shared__ float part[4];
    if (lane == 0) part[wid] = acc;
    __syncthreads();
    if (threadIdx.x == 0) {
        out[row] = (part[0] + part[1]) + (part[2] + part[3]);
    }
}

// ---------------------------------------------------------------------------
extern "C" void kernel_launch(void* const* d_in, const int* in_sizes, int n_in,
                              void* d_out, int out_size) {
    const float* x           = (const float*)d_in[0];
    const float* ssm_state   = (const float*)d_in[1];
    const float* conv_buffer = (const float*)d_in[2];
    const float* W_in        = (const float*)d_in[3];
    const float* conv_w      = (const float*)d_in[4];
    const float* conv_b      = (const float*)d_in[5];
    const float* W_xp        = (const float*)d_in[6];
    const float* W_dt        = (const float*)d_in[7];
    const float* b_dt        = (const float*)d_in[8];
    const float* A_log       = (const float*)d_in[9];
    const float* D_param     = (const float*)d_in[10];
    const float* W_out       = (const float*)d_in[11];

    float* out   = (float*)d_out;               // [0, 4096)
    float* new_h = (float*)d_out + D_MODEL;     // [4096, 4096 + 8192*16)

    // K1: W_in GEMV + fused conv/SiLU (2 warps/row -> 4096 blocks)
    gemv_win_fused<<<(2 * D_INNER) / 4, 256>>>(W_in, x, conv_buffer, conv_w, conv_b);

    // K2: xp = W_xp @ x_conv (40 blocks x 1024)
    gemv_xp<<<XP_ROWS, 1024>>>(W_xp);

    // K3: state update + y (128 blocks x 64 threads)
    ssm_update_kernel<<<D_INNER / 64, 64>>>(W_dt, b_dt, A_log, ssm_state,
                                            D_param, new_h);

    // K4: out = W_out @ y (1 row per 128-thr block -> 4096 blocks)
    gemv_wout<<<D_MODEL, 128>>>(W_out, out);
}